// round 1
// baseline (speedup 1.0000x reference)
#include <cuda_runtime.h>
#include <math.h>

#define Bz 32
#define Lz 512
#define Ez 512
#define NMARKz 4
#define Dz 512
#define Hz 8
#define DFFz 2048
#define NHASHz 4
#define NTOK 516
#define TPAD 520
#define DHz 64
#define NBz 130
#define NCH 520
#define BHz 256          // B*H
#define FLATz 2080       // NHASH*TPAD
#define ROTC 260         // NHASH*65
#define ROTCP 320        // padded to multiple of 64

// ---------------- scratch (static device globals; no allocation) ----------------
static __device__ float g_mean[Bz * Ez];
static __device__ float g_std[Bz * Ez];
static __device__ float g_tok[(size_t)Bz * NTOK * Lz];
static __device__ float g_X[(size_t)Bz * TPAD * Dz];
static __device__ float g_QK[(size_t)BHz * TPAD * DHz];
static __device__ float g_V[(size_t)BHz * TPAD * DHz];
static __device__ float g_rotT[ROTCP * DHz];
static __device__ float g_ROT[(size_t)BHz * TPAD * ROTCP];
static __device__ int   g_key[(size_t)BHz * FLATz];
static __device__ int   g_stick[(size_t)BHz * FLATz];
static __device__ float g_O4[(size_t)BHz * NHASHz * TPAD * DHz];
static __device__ float g_LSE4[(size_t)BHz * NHASHz * TPAD];
static __device__ float g_AO[(size_t)Bz * TPAD * Dz];
static __device__ float g_Y[(size_t)Bz * NTOK * Dz];
static __device__ float g_H1[(size_t)Bz * NTOK * DFFz];
static __device__ float g_dec[Bz];

// ---------------- RevIN stats: mean/std per (b,e) over L ----------------
__global__ void stats_kernel(const float* __restrict__ x) {
    int w = (blockIdx.x * blockDim.x + threadIdx.x) >> 5;
    int lane = threadIdx.x & 31;
    if (w >= Bz * Ez) return;
    int b = w / Ez, e = w % Ez;
    const float* p = x + (size_t)b * Lz * Ez + e;
    float s = 0.f, ss = 0.f;
    for (int l = lane; l < Lz; l += 32) {
        float v = p[(size_t)l * Ez];
        s += v; ss += v * v;
    }
    #pragma unroll
    for (int o = 16; o; o >>= 1) {
        s += __shfl_xor_sync(0xffffffffu, s, o);
        ss += __shfl_xor_sync(0xffffffffu, ss, o);
    }
    if (lane == 0) {
        float m = s / Lz;
        float var = ss / Lz - m * m;
        g_mean[w] = m;
        g_std[w] = sqrtf(var + 1e-5f);
    }
}

// ---------------- build inverted tokens: TOK[b][n][l] ----------------
__global__ void tok_kernel(const float* __restrict__ x_enc, const float* __restrict__ x_mark) {
    int idx = blockIdx.x * blockDim.x + threadIdx.x;
    if (idx >= Bz * NTOK * Lz) return;
    int l = idx % Lz;
    int n = (idx / Lz) % NTOK;
    int b = idx / (Lz * NTOK);
    float v;
    if (n < Ez) {
        v = (x_enc[((size_t)b * Lz + l) * Ez + n] - g_mean[b * Ez + n]) / g_std[b * Ez + n];
    } else {
        v = x_mark[((size_t)b * Lz + l) * NMARKz + (n - Ez)];
    }
    g_tok[idx] = v;
}

// ---------------- zero padding rows of X (516..519 per batch) ----------------
__global__ void zero_pad_kernel() {
    int idx = blockIdx.x * blockDim.x + threadIdx.x;
    if (idx >= Bz * 4 * Dz) return;
    int d = idx % Dz;
    int t = (idx / Dz) % 4;
    int b = idx / (Dz * 4);
    g_X[((size_t)b * TPAD + NTOK + t) * Dz + d] = 0.f;
}

// ---------------- generic tiled GEMM: C = A @ W^T (+bias)(+relu) ----------------
// A row remap: a_fixed_t>=0 -> row m uses A + (m*a_pitch + a_fixed_t)*K
//              else a_seg_len>0 -> b=m/a_seg_len,r=m%a_seg_len -> (b*a_pitch+r)*K
//              else plain m*K.
// C modes: 0 plain [M,N]; 1 seg remap (b*c_pitch + r)*N; 2 head split [b,h,t,dh] (t=m%c_pitch)
__global__ void __launch_bounds__(256) gemm_kernel(
    const float* __restrict__ A, const float* __restrict__ W,
    const float* __restrict__ bias, float* __restrict__ C,
    int M, int N, int K,
    int a_seg_len, int a_pitch, int a_fixed_t,
    int c_mode, int c_seg_len, int c_pitch, int relu)
{
    __shared__ float As[16][64];
    __shared__ float Bs[16][64];
    int tid = threadIdx.x;
    int m0 = blockIdx.y * 64, n0 = blockIdx.x * 64;
    int ty = tid >> 4, tx = tid & 15;
    float acc[4][4];
    #pragma unroll
    for (int i = 0; i < 4; i++)
        #pragma unroll
        for (int j = 0; j < 4; j++) acc[i][j] = 0.f;

    int lr = tid >> 2;          // 0..63 row within tile
    int lk = (tid & 3) * 4;     // 0,4,8,12
    int gm_l = m0 + lr;
    const float* arow = nullptr;
    if (gm_l < M) {
        if (a_fixed_t >= 0) arow = A + ((size_t)gm_l * a_pitch + a_fixed_t) * (size_t)K;
        else if (a_seg_len > 0) arow = A + ((size_t)(gm_l / a_seg_len) * a_pitch + (gm_l % a_seg_len)) * (size_t)K;
        else arow = A + (size_t)gm_l * K;
    }
    const float* wrow = W + (size_t)(n0 + lr) * K;

    for (int k0 = 0; k0 < K; k0 += 16) {
        float4 av = arow ? *(const float4*)(arow + k0 + lk) : make_float4(0.f, 0.f, 0.f, 0.f);
        float4 wv = *(const float4*)(wrow + k0 + lk);
        __syncthreads();
        As[lk + 0][lr] = av.x; As[lk + 1][lr] = av.y; As[lk + 2][lr] = av.z; As[lk + 3][lr] = av.w;
        Bs[lk + 0][lr] = wv.x; Bs[lk + 1][lr] = wv.y; Bs[lk + 2][lr] = wv.z; Bs[lk + 3][lr] = wv.w;
        __syncthreads();
        #pragma unroll
        for (int k = 0; k < 16; k++) {
            float4 a = *(const float4*)&As[k][ty * 4];
            float4 b = *(const float4*)&Bs[k][tx * 4];
            acc[0][0] += a.x * b.x; acc[0][1] += a.x * b.y; acc[0][2] += a.x * b.z; acc[0][3] += a.x * b.w;
            acc[1][0] += a.y * b.x; acc[1][1] += a.y * b.y; acc[1][2] += a.y * b.z; acc[1][3] += a.y * b.w;
            acc[2][0] += a.z * b.x; acc[2][1] += a.z * b.y; acc[2][2] += a.z * b.z; acc[2][3] += a.z * b.w;
            acc[3][0] += a.w * b.x; acc[3][1] += a.w * b.y; acc[3][2] += a.w * b.z; acc[3][3] += a.w * b.w;
        }
    }

    #pragma unroll
    for (int i = 0; i < 4; i++) {
        int gm = m0 + ty * 4 + i;
        if (gm >= M) continue;
        #pragma unroll
        for (int j = 0; j < 4; j++) {
            int gn = n0 + tx * 4 + j;
            float v = acc[i][j] + (bias ? bias[gn] : 0.f);
            if (relu) v = fmaxf(v, 0.f);
            size_t off;
            if (c_mode == 2) {
                int b = gm / c_pitch, t = gm % c_pitch;
                off = (((size_t)(b * Hz + (gn >> 6))) * c_pitch + t) * DHz + (gn & 63);
            } else if (c_mode == 1) {
                int b = gm / c_seg_len, r = gm % c_seg_len;
                off = ((size_t)b * c_pitch + r) * (size_t)N + gn;
            } else {
                off = (size_t)gm * N + gn;
            }
            C[off] = v;
        }
    }
}

// ---------------- transpose rot[f][h][i] -> rotT[n=h*65+i][f] (zero-pad to 320) ----------------
__global__ void rotT_kernel(const float* __restrict__ rot) {
    int idx = blockIdx.x * blockDim.x + threadIdx.x;
    if (idx >= ROTCP * DHz) return;
    int f = idx % DHz;
    int n = idx / DHz;
    float v = 0.f;
    if (n < ROTC) {
        int h = n / 65, i = n % 65;
        v = rot[((size_t)f * NHASHz + h) * 65 + i];
    }
    g_rotT[(size_t)n * DHz + f] = v;
}

// ---------------- argmax over [rotated, -rotated] per (row,h) -> bucket key ----------------
__global__ void argmax_kernel() {
    int wid = (blockIdx.x * blockDim.x + threadIdx.x) >> 5;
    if (wid >= BHz * TPAD * NHASHz) return;
    int lane = threadIdx.x & 31;
    int h = wid % NHASHz;
    int row = wid / NHASHz;             // bh*TPAD + t
    const float* rp = g_ROT + (size_t)row * ROTCP + h * 65;
    float best = -3.402823e38f;
    int bidx = 0x7fffffff;
    for (int i = lane; i < 65; i += 32) {
        float dp = rp[i];
        if (dp > best || (dp == best && i < bidx)) { best = dp; bidx = i; }
        float nd = -dp; int ni = 65 + i;
        if (nd > best || (nd == best && ni < bidx)) { best = nd; bidx = ni; }
    }
    #pragma unroll
    for (int o = 16; o; o >>= 1) {
        float ov = __shfl_xor_sync(0xffffffffu, best, o);
        int oi = __shfl_xor_sync(0xffffffffu, bidx, o);
        if (ov > best || (ov == best && oi < bidx)) { best = ov; bidx = oi; }
    }
    if (lane == 0) {
        int bh = row / TPAD, t = row % TPAD;
        g_key[(size_t)bh * FLATz + h * TPAD + t] = (bidx + h * NBz) * TPAD + t;
    }
}

// ---------------- bitonic sort of 2080 (key, flat-index) pairs per bh ----------------
__global__ void __launch_bounds__(1024) sort_kernel() {
    int bh = blockIdx.x;
    __shared__ int sk[4096];
    __shared__ int sv[4096];
    int tid = threadIdx.x;
    for (int i = tid; i < 4096; i += 1024) {
        if (i < FLATz) { sk[i] = g_key[(size_t)bh * FLATz + i]; sv[i] = i; }
        else { sk[i] = 0x7fffffff; sv[i] = i; }
    }
    __syncthreads();
    for (int k = 2; k <= 4096; k <<= 1) {
        for (int j = k >> 1; j > 0; j >>= 1) {
            for (int i = tid; i < 4096; i += 1024) {
                int ixj = i ^ j;
                if (ixj > i) {
                    bool asc = ((i & k) == 0);
                    int a = sk[i], bb = sk[ixj];
                    if ((a > bb) == asc) {
                        sk[i] = bb; sk[ixj] = a;
                        int t = sv[i]; sv[i] = sv[ixj]; sv[ixj] = t;
                    }
                }
            }
            __syncthreads();
        }
    }
    for (int i = tid; i < FLATz; i += 1024) g_stick[(size_t)bh * FLATz + i] = sv[i];
}

// ---------------- chunked LSH attention: one warp per (bh, chunk) ----------------
__global__ void chunk_attn_kernel() {
    int wid = (blockIdx.x * blockDim.x + threadIdx.x) >> 5;
    if (wid >= BHz * NCH) return;
    int lane = threadIdx.x & 31;
    int bh = wid / NCH, c = wid % NCH;
    int prev = (c == 0) ? (NCH - 1) : (c - 1);
    const int* st = g_stick + (size_t)bh * FLATz;

    int fq[4], tq[4], tk[8];
    #pragma unroll
    for (int i = 0; i < 4; i++) { fq[i] = st[c * 4 + i]; tq[i] = fq[i] % TPAD; }
    #pragma unroll
    for (int j = 0; j < 4; j++) tk[j] = tq[j];
    #pragma unroll
    for (int j = 0; j < 4; j++) { int f = st[prev * 4 + j]; tk[4 + j] = f % TPAD; }

    const float* QKb = g_QK + (size_t)bh * TPAD * DHz;
    const float* Vb  = g_V  + (size_t)bh * TPAD * DHz;
    int d0 = lane * 2;

    float2 q[4], k8[8], v8[8];
    #pragma unroll
    for (int i = 0; i < 4; i++) q[i] = *(const float2*)&QKb[(size_t)tq[i] * DHz + d0];
    #pragma unroll
    for (int j = 0; j < 8; j++) {
        k8[j] = *(const float2*)&QKb[(size_t)tk[j] * DHz + d0];
        v8[j] = *(const float2*)&Vb[(size_t)tk[j] * DHz + d0];
    }

    // key norms (shared-QK: keys = unit-normalized queries)
    float ns[8];
    #pragma unroll
    for (int j = 0; j < 8; j++) ns[j] = k8[j].x * k8[j].x + k8[j].y * k8[j].y;
    #pragma unroll
    for (int o = 16; o; o >>= 1)
        #pragma unroll
        for (int j = 0; j < 8; j++) ns[j] += __shfl_xor_sync(0xffffffffu, ns[j], o);
    float rn[8];
    #pragma unroll
    for (int j = 0; j < 8; j++) rn[j] = 1.0f / sqrtf(fmaxf(ns[j], 1e-24f));

    // dots [4][8]
    float dt[4][8];
    #pragma unroll
    for (int i = 0; i < 4; i++)
        #pragma unroll
        for (int j = 0; j < 8; j++)
            dt[i][j] = q[i].x * k8[j].x + q[i].y * k8[j].y;
    #pragma unroll
    for (int o = 16; o; o >>= 1)
        #pragma unroll
        for (int i = 0; i < 4; i++)
            #pragma unroll
            for (int j = 0; j < 8; j++)
                dt[i][j] += __shfl_xor_sync(0xffffffffu, dt[i][j], o);

    #pragma unroll
    for (int i = 0; i < 4; i++)
        #pragma unroll
        for (int j = 0; j < 8; j++)
            dt[i][j] = (tq[i] == tk[j]) ? -5e4f : dt[i][j] * rn[j] * 0.125f;

    #pragma unroll
    for (int i = 0; i < 4; i++) {
        float mx = -3.402823e38f;
        #pragma unroll
        for (int j = 0; j < 8; j++) mx = fmaxf(mx, dt[i][j]);
        float p[8], se = 0.f;
        #pragma unroll
        for (int j = 0; j < 8; j++) { p[j] = expf(dt[i][j] - mx); se += p[j]; }
        float lse = logf(se) + mx;
        float inv = 1.0f / se;
        float2 o = make_float2(0.f, 0.f);
        #pragma unroll
        for (int j = 0; j < 8; j++) {
            float w = p[j] * inv;
            o.x += w * v8[j].x;
            o.y += w * v8[j].y;
        }
        int h = fq[i] / TPAD;
        size_t obase = (((size_t)(bh * NHASHz + h)) * TPAD + tq[i]);
        *(float2*)&g_O4[obase * DHz + d0] = o;
        if (lane == 0) g_LSE4[obase] = lse;
    }
}

// ---------------- combine hash rounds -> AO[b][t][h*64+dh] ----------------
__global__ void combine_kernel() {
    int gid = blockIdx.x * blockDim.x + threadIdx.x;
    int idx = gid >> 6;
    int d = gid & 63;
    if (idx >= BHz * TPAD) return;
    int bh = idx / TPAD, t = idx % TPAD;
    float l[NHASHz];
    float mx = -3.402823e38f;
    #pragma unroll
    for (int h = 0; h < NHASHz; h++) {
        l[h] = g_LSE4[((size_t)bh * NHASHz + h) * TPAD + t];
        mx = fmaxf(mx, l[h]);
    }
    float w[NHASHz], se = 0.f;
    #pragma unroll
    for (int h = 0; h < NHASHz; h++) { w[h] = expf(l[h] - mx); se += w[h]; }
    float inv = 1.0f / se;
    float o = 0.f;
    #pragma unroll
    for (int h = 0; h < NHASHz; h++)
        o += w[h] * inv * g_O4[(((size_t)bh * NHASHz + h) * TPAD + t) * DHz + d];
    int b = bh / Hz, head = bh % Hz;
    g_AO[((size_t)b * TPAD + t) * Dz + head * DHz + d] = o;
}

// ---------------- residual + LayerNorm, writes back into X ----------------
__global__ void ln_res_kernel(const float* __restrict__ g, const float* __restrict__ bb, int t_fixed) {
    int r = blockIdx.x;
    int b, t;
    if (t_fixed >= 0) { b = r; t = t_fixed; }
    else { b = r / NTOK; t = r % NTOK; }
    float* xr = g_X + ((size_t)b * TPAD + t) * Dz;
    const float* yr = g_Y + (size_t)r * Dz;
    int tid = threadIdx.x;
    float v0 = xr[tid] + yr[tid];
    float v1 = xr[tid + 256] + yr[tid + 256];
    float s = v0 + v1, ss = v0 * v0 + v1 * v1;
    __shared__ float shs[8], shss[8];
    __shared__ float s_mean, s_rstd;
    int lane = tid & 31, w = tid >> 5;
    #pragma unroll
    for (int o = 16; o; o >>= 1) {
        s += __shfl_xor_sync(0xffffffffu, s, o);
        ss += __shfl_xor_sync(0xffffffffu, ss, o);
    }
    if (lane == 0) { shs[w] = s; shss[w] = ss; }
    __syncthreads();
    if (tid == 0) {
        float S = 0.f, SS = 0.f;
        #pragma unroll
        for (int i = 0; i < 8; i++) { S += shs[i]; SS += shss[i]; }
        float m = S / Dz;
        float var = SS / Dz - m * m;
        s_mean = m;
        s_rstd = 1.0f / sqrtf(var + 1e-5f);
    }
    __syncthreads();
    float m = s_mean, rs = s_rstd;
    xr[tid]       = (v0 - m) * rs * g[tid]       + bb[tid];
    xr[tid + 256] = (v1 - m) * rs * g[tid + 256] + bb[tid + 256];
}

// ---------------- final LN(row 515) + projection -> dec[b] ----------------
__global__ void final_kernel(const float* __restrict__ gF, const float* __restrict__ bF,
                             const float* __restrict__ Wp, const float* __restrict__ bp) {
    int b = blockIdx.x;
    int tid = threadIdx.x;
    const float* xr = g_X + ((size_t)b * TPAD + (NTOK - 1)) * Dz;
    float v0 = xr[tid], v1 = xr[tid + 256];
    float s = v0 + v1, ss = v0 * v0 + v1 * v1;
    __shared__ float shs[8], shss[8], shp[8];
    __shared__ float s_mean, s_rstd;
    int lane = tid & 31, w = tid >> 5;
    #pragma unroll
    for (int o = 16; o; o >>= 1) {
        s += __shfl_xor_sync(0xffffffffu, s, o);
        ss += __shfl_xor_sync(0xffffffffu, ss, o);
    }
    if (lane == 0) { shs[w] = s; shss[w] = ss; }
    __syncthreads();
    if (tid == 0) {
        float S = 0.f, SS = 0.f;
        #pragma unroll
        for (int i = 0; i < 8; i++) { S += shs[i]; SS += shss[i]; }
        float m = S / Dz;
        float var = SS / Dz - m * m;
        s_mean = m;
        s_rstd = 1.0f / sqrtf(var + 1e-5f);
    }
    __syncthreads();
    float m = s_mean, rs = s_rstd;
    float y0 = (v0 - m) * rs * gF[tid] + bF[tid];
    float y1 = (v1 - m) * rs * gF[tid + 256] + bF[tid + 256];
    float p = y0 * Wp[tid] + y1 * Wp[tid + 256];
    #pragma unroll
    for (int o = 16; o; o >>= 1) p += __shfl_xor_sync(0xffffffffu, p, o);
    if (lane == 0) shp[w] = p;
    __syncthreads();
    if (tid == 0) {
        float P = 0.f;
        #pragma unroll
        for (int i = 0; i < 8; i++) P += shp[i];
        g_dec[b] = P + bp[0];
    }
}

// ---------------- broadcast output: out[i][j][e] = dec[j]*std[i,e] + mean[i,e] ----------------
__global__ void out_kernel(float* __restrict__ out) {
    int idx = blockIdx.x * blockDim.x + threadIdx.x;
    if (idx >= Bz * Bz * Ez) return;
    int e = idx % Ez;
    int j = (idx / Ez) % Bz;
    int i = idx / (Ez * Bz);
    out[idx] = g_dec[j] * g_std[i * Ez + e] + g_mean[i * Ez + e];
}

// ================================================================================
extern "C" void kernel_launch(void* const* d_in, const int* in_sizes, int n_in,
                              void* d_out, int out_size) {
    const float* x_enc  = (const float*)d_in[0];
    const float* x_mark = (const float*)d_in[1];
    const float* W_emb  = (const float*)d_in[2];
    const float* b_emb  = (const float*)d_in[3];
    const float* Wqk    = (const float*)d_in[4];
    const float* Wv     = (const float*)d_in[5];
    const float* Wo     = (const float*)d_in[6];
    const float* bo     = (const float*)d_in[7];
    const float* Wc1    = (const float*)d_in[8];
    const float* bc1    = (const float*)d_in[9];
    const float* Wc2    = (const float*)d_in[10];
    const float* bc2    = (const float*)d_in[11];
    const float* g1     = (const float*)d_in[12];
    const float* b1     = (const float*)d_in[13];
    const float* g2     = (const float*)d_in[14];
    const float* b2     = (const float*)d_in[15];
    const float* gF     = (const float*)d_in[16];
    const float* bF     = (const float*)d_in[17];
    const float* Wp     = (const float*)d_in[18];
    const float* bp     = (const float*)d_in[19];
    const float* rot    = (const float*)d_in[20];
    float* out = (float*)d_out;

    float *p_tok, *p_X, *p_QK, *p_V, *p_rotT, *p_ROT, *p_AO, *p_Y, *p_H1;
    cudaGetSymbolAddress((void**)&p_tok,  g_tok);
    cudaGetSymbolAddress((void**)&p_X,    g_X);
    cudaGetSymbolAddress((void**)&p_QK,   g_QK);
    cudaGetSymbolAddress((void**)&p_V,    g_V);
    cudaGetSymbolAddress((void**)&p_rotT, g_rotT);
    cudaGetSymbolAddress((void**)&p_ROT,  g_ROT);
    cudaGetSymbolAddress((void**)&p_AO,   g_AO);
    cudaGetSymbolAddress((void**)&p_Y,    g_Y);
    cudaGetSymbolAddress((void**)&p_H1,   g_H1);

    // ---- RevIN + tokenization + embedding ----
    stats_kernel<<<2048, 256>>>(x_enc);
    tok_kernel<<<(Bz * NTOK * Lz + 255) / 256, 256>>>(x_enc, x_mark);
    zero_pad_kernel<<<(Bz * 4 * Dz + 255) / 256, 256>>>();
    // X[:, :516, :] = TOK @ W_emb^T + b_emb
    gemm_kernel<<<dim3(Dz / 64, (Bz * NTOK) / 64), 256>>>(
        p_tok, W_emb, b_emb, p_X, Bz * NTOK, Dz, Lz,
        0, 0, -1, 1, NTOK, TPAD, 0);

    for (int l = 0; l < 2; l++) {
        const float* Wqk_l = Wqk + (size_t)l * Dz * Dz;
        const float* Wv_l  = Wv  + (size_t)l * Dz * Dz;
        const float* Wo_l  = Wo  + (size_t)l * Dz * Dz;
        const float* bo_l  = bo  + (size_t)l * Dz;
        const float* Wc1_l = Wc1 + (size_t)l * DFFz * Dz;
        const float* bc1_l = bc1 + (size_t)l * DFFz;
        const float* Wc2_l = Wc2 + (size_t)l * Dz * DFFz;
        const float* bc2_l = bc2 + (size_t)l * Dz;
        const float* g1_l = g1 + (size_t)l * Dz;
        const float* b1_l = b1 + (size_t)l * Dz;
        const float* g2_l = g2 + (size_t)l * Dz;
        const float* b2_l = b2 + (size_t)l * Dz;
        const float* rot_l = rot + (size_t)l * DHz * NHASHz * (NBz / 2);

        // QK / V projections (head-split output [bh, t, dh])
        gemm_kernel<<<dim3(Dz / 64, (Bz * TPAD) / 64), 256>>>(
            p_X, Wqk_l, nullptr, p_QK, Bz * TPAD, Dz, Dz,
            0, 0, -1, 2, 0, TPAD, 0);
        gemm_kernel<<<dim3(Dz / 64, (Bz * TPAD) / 64), 256>>>(
            p_X, Wv_l, nullptr, p_V, Bz * TPAD, Dz, Dz,
            0, 0, -1, 2, 0, TPAD, 0);

        // LSH bucketing: rotated = QK @ rotT^T, then argmax -> sort keys
        rotT_kernel<<<(ROTCP * DHz + 255) / 256, 256>>>(rot_l);
        gemm_kernel<<<dim3(ROTCP / 64, (BHz * TPAD) / 64), 256>>>(
            p_QK, p_rotT, nullptr, p_ROT, BHz * TPAD, ROTCP, DHz,
            0, 0, -1, 0, 0, 0, 0);
        argmax_kernel<<<(BHz * TPAD * NHASHz * 32 + 255) / 256, 256>>>();
        sort_kernel<<<BHz, 1024>>>();
        chunk_attn_kernel<<<(BHz * NCH) / 4, 128>>>();
        combine_kernel<<<(BHz * TPAD * 64) / 256, 256>>>();

        if (l == 0) {
            // full-width path
            gemm_kernel<<<dim3(Dz / 64, (Bz * NTOK) / 64), 256>>>(
                p_AO, Wo_l, bo_l, p_Y, Bz * NTOK, Dz, Dz,
                NTOK, TPAD, -1, 0, 0, 0, 0);
            ln_res_kernel<<<Bz * NTOK, 256>>>(g1_l, b1_l, -1);
            gemm_kernel<<<dim3(DFFz / 64, (Bz * NTOK) / 64), 256>>>(
                p_X, Wc1_l, bc1_l, p_H1, Bz * NTOK, DFFz, Dz,
                NTOK, TPAD, -1, 0, 0, 0, 1);
            gemm_kernel<<<dim3(Dz / 64, (Bz * NTOK) / 64), 256>>>(
                p_H1, Wc2_l, bc2_l, p_Y, Bz * NTOK, Dz, DFFz,
                0, 0, -1, 0, 0, 0, 0);
            ln_res_kernel<<<Bz * NTOK, 256>>>(g2_l, b2_l, -1);
        } else {
            // last layer: only token 515 feeds the output head
            gemm_kernel<<<dim3(Dz / 64, 1), 256>>>(
                p_AO, Wo_l, bo_l, p_Y, Bz, Dz, Dz,
                0, TPAD, NTOK - 1, 0, 0, 0, 0);
            ln_res_kernel<<<Bz, 256>>>(g1_l, b1_l, NTOK - 1);
            gemm_kernel<<<dim3(DFFz / 64, 1), 256>>>(
                p_X, Wc1_l, bc1_l, p_H1, Bz, DFFz, Dz,
                0, TPAD, NTOK - 1, 0, 0, 0, 1);
            gemm_kernel<<<dim3(Dz / 64, 1), 256>>>(
                p_H1, Wc2_l, bc2_l, p_Y, Bz, Dz, DFFz,
                0, 0, -1, 0, 0, 0, 0);
            ln_res_kernel<<<Bz, 256>>>(g2_l, b2_l, NTOK - 1);
        }
    }

    final_kernel<<<Bz, 256>>>(gF, bF, Wp, bp);
    out_kernel<<<(Bz * Bz * Ez + 255) / 256, 256>>>(out);
}

// round 2
// speedup vs baseline: 1.2549x; 1.2549x over previous
#include <cuda_runtime.h>
#include <math.h>

#define Bz 32
#define Lz 512
#define Ez 512
#define NMARKz 4
#define Dz 512
#define Hz 8
#define DFFz 2048
#define NHASHz 4
#define NTOK 516
#define TPAD 520
#define DHz 64
#define NBz 130
#define NCH 520
#define BHz 256          // B*H
#define FLATz 2080       // NHASH*TPAD
#define ROTC 260         // NHASH*65
#define ROTCP 384        // padded to multiple of 128

// ---------------- scratch (static device globals; no allocation) ----------------
static __device__ float g_mean[Bz * Ez];
static __device__ float g_std[Bz * Ez];
static __device__ float g_tok[(size_t)Bz * NTOK * Lz];
static __device__ float g_X[(size_t)Bz * TPAD * Dz];
static __device__ float g_QK[(size_t)BHz * TPAD * DHz];
static __device__ float g_V[(size_t)BHz * TPAD * DHz];
static __device__ float g_rotT[ROTCP * DHz];
static __device__ float g_ROT[(size_t)BHz * TPAD * ROTCP];
static __device__ int   g_key[(size_t)BHz * FLATz];
static __device__ int   g_stick[(size_t)BHz * FLATz];
static __device__ int   g_sel[BHz * NHASHz];
static __device__ float g_O4[(size_t)BHz * NHASHz * TPAD * DHz];
static __device__ float g_LSE4[(size_t)BHz * NHASHz * TPAD];
static __device__ float g_AO[(size_t)Bz * TPAD * Dz];
static __device__ float g_Y[(size_t)Bz * NTOK * Dz];
static __device__ float g_H1[(size_t)Bz * NTOK * DFFz];
static __device__ float g_dec[Bz];

// ---------------- RevIN stats: mean/std per (b,e) over L ----------------
__global__ void stats_kernel(const float* __restrict__ x) {
    int w = (blockIdx.x * blockDim.x + threadIdx.x) >> 5;
    int lane = threadIdx.x & 31;
    if (w >= Bz * Ez) return;
    int b = w / Ez, e = w % Ez;
    const float* p = x + (size_t)b * Lz * Ez + e;
    float s = 0.f, ss = 0.f;
    for (int l = lane; l < Lz; l += 32) {
        float v = p[(size_t)l * Ez];
        s += v; ss += v * v;
    }
    #pragma unroll
    for (int o = 16; o; o >>= 1) {
        s += __shfl_xor_sync(0xffffffffu, s, o);
        ss += __shfl_xor_sync(0xffffffffu, ss, o);
    }
    if (lane == 0) {
        float m = s / Lz;
        float var = ss / Lz - m * m;
        g_mean[w] = m;
        g_std[w] = sqrtf(var + 1e-5f);
    }
}

// ---------------- build inverted tokens: TOK[b][n][l] ----------------
__global__ void tok_kernel(const float* __restrict__ x_enc, const float* __restrict__ x_mark) {
    int idx = blockIdx.x * blockDim.x + threadIdx.x;
    if (idx >= Bz * NTOK * Lz) return;
    int l = idx % Lz;
    int n = (idx / Lz) % NTOK;
    int b = idx / (Lz * NTOK);
    float v;
    if (n < Ez) {
        v = (x_enc[((size_t)b * Lz + l) * Ez + n] - g_mean[b * Ez + n]) / g_std[b * Ez + n];
    } else {
        v = x_mark[((size_t)b * Lz + l) * NMARKz + (n - Ez)];
    }
    g_tok[idx] = v;
}

// ---------------- zero padding rows of X (516..519 per batch) ----------------
__global__ void zero_pad_kernel() {
    int idx = blockIdx.x * blockDim.x + threadIdx.x;
    if (idx >= Bz * 4 * Dz) return;
    int d = idx % Dz;
    int t = (idx / Dz) % 4;
    int b = idx / (Dz * 4);
    g_X[((size_t)b * TPAD + NTOK + t) * Dz + d] = 0.f;
}

// ---------------- 128x128x8 tiled GEMM: C = A @ W^T (+bias)(+relu) ----------------
// A row remap: a_fixed_t>=0 -> row m uses A + (m*a_pitch + a_fixed_t)*K
//              else a_seg_len>0 -> b=m/a_seg_len,r=m%a_seg_len -> (b*a_pitch+r)*K
//              else plain m*K.
// C modes: 0 plain [M,N]; 1 seg remap (b*c_pitch + r)*N; 2 head split [b,h,t,dh]
__global__ void __launch_bounds__(256, 2) gemm128(
    const float* __restrict__ A, const float* __restrict__ W,
    const float* __restrict__ bias, float* __restrict__ C,
    int M, int N, int K,
    int a_seg_len, int a_pitch, int a_fixed_t,
    int c_mode, int c_seg, int c_pitch, int relu)
{
    __shared__ float As[2][8][128];
    __shared__ float Bs[2][8][128];
    const int tid = threadIdx.x;
    const int m0 = blockIdx.y * 128, n0 = blockIdx.x * 128;
    const int tx = tid & 15, ty = tid >> 4;
    float acc[8][8];
    #pragma unroll
    for (int i = 0; i < 8; i++)
        #pragma unroll
        for (int j = 0; j < 8; j++) acc[i][j] = 0.f;

    const int lr = tid >> 1;          // 0..127
    const int lk = (tid & 1) * 4;     // 0 or 4
    const int am = m0 + lr;
    const float* arow = nullptr;
    if (am < M) {
        if (a_fixed_t >= 0) arow = A + ((size_t)am * a_pitch + a_fixed_t) * (size_t)K;
        else if (a_seg_len > 0) arow = A + ((size_t)(am / a_seg_len) * a_pitch + (am % a_seg_len)) * (size_t)K;
        else arow = A + (size_t)am * K;
    }
    const float* wrow = W + (size_t)(n0 + lr) * K;

    // prologue: load tile 0
    float4 av = arow ? *(const float4*)(arow + lk) : make_float4(0.f, 0.f, 0.f, 0.f);
    float4 wv = *(const float4*)(wrow + lk);
    As[0][lk + 0][lr] = av.x; As[0][lk + 1][lr] = av.y; As[0][lk + 2][lr] = av.z; As[0][lk + 3][lr] = av.w;
    Bs[0][lk + 0][lr] = wv.x; Bs[0][lk + 1][lr] = wv.y; Bs[0][lk + 2][lr] = wv.z; Bs[0][lk + 3][lr] = wv.w;
    __syncthreads();

    int buf = 0;
    for (int k0 = 0; k0 < K; k0 += 8) {
        const bool more = (k0 + 8 < K);
        float4 av2, wv2;
        if (more) {
            av2 = arow ? *(const float4*)(arow + k0 + 8 + lk) : make_float4(0.f, 0.f, 0.f, 0.f);
            wv2 = *(const float4*)(wrow + k0 + 8 + lk);
        }
        #pragma unroll
        for (int k = 0; k < 8; k++) {
            float4 a0 = *(const float4*)&As[buf][k][ty * 8];
            float4 a1 = *(const float4*)&As[buf][k][ty * 8 + 4];
            float4 b0 = *(const float4*)&Bs[buf][k][tx * 8];
            float4 b1 = *(const float4*)&Bs[buf][k][tx * 8 + 4];
            float a[8] = {a0.x, a0.y, a0.z, a0.w, a1.x, a1.y, a1.z, a1.w};
            float b[8] = {b0.x, b0.y, b0.z, b0.w, b1.x, b1.y, b1.z, b1.w};
            #pragma unroll
            for (int i = 0; i < 8; i++)
                #pragma unroll
                for (int j = 0; j < 8; j++)
                    acc[i][j] += a[i] * b[j];
        }
        if (more) {
            int nb = buf ^ 1;
            As[nb][lk + 0][lr] = av2.x; As[nb][lk + 1][lr] = av2.y; As[nb][lk + 2][lr] = av2.z; As[nb][lk + 3][lr] = av2.w;
            Bs[nb][lk + 0][lr] = wv2.x; Bs[nb][lk + 1][lr] = wv2.y; Bs[nb][lk + 2][lr] = wv2.z; Bs[nb][lk + 3][lr] = wv2.w;
            __syncthreads();
            buf = nb;
        }
    }

    // epilogue
    const int gn0 = n0 + tx * 8;
    float bb[8];
    #pragma unroll
    for (int j = 0; j < 8; j++) bb[j] = bias ? bias[gn0 + j] : 0.f;

    #pragma unroll
    for (int i = 0; i < 8; i++) {
        int gm = m0 + ty * 8 + i;
        if (gm >= M) continue;
        size_t base;
        if (c_mode == 2) {
            int b = gm / c_pitch, t = gm % c_pitch;
            int head = gn0 >> 6;
            base = (((size_t)(b * Hz + head)) * c_pitch + t) * DHz + (gn0 & 63);
        } else if (c_mode == 1) {
            int b = gm / c_seg, r = gm % c_seg;
            base = ((size_t)b * c_pitch + r) * (size_t)N + gn0;
        } else {
            base = (size_t)gm * N + gn0;
        }
        #pragma unroll
        for (int jj = 0; jj < 8; jj += 4) {
            float4 v;
            v.x = acc[i][jj + 0] + bb[jj + 0];
            v.y = acc[i][jj + 1] + bb[jj + 1];
            v.z = acc[i][jj + 2] + bb[jj + 2];
            v.w = acc[i][jj + 3] + bb[jj + 3];
            if (relu) {
                v.x = fmaxf(v.x, 0.f); v.y = fmaxf(v.y, 0.f);
                v.z = fmaxf(v.z, 0.f); v.w = fmaxf(v.w, 0.f);
            }
            *(float4*)&C[base + jj] = v;
        }
    }
}

// ---------------- transpose rot[f][h][i] -> rotT[n=h*65+i][f] (zero-pad to 384) ----------------
__global__ void rotT_kernel(const float* __restrict__ rot) {
    int idx = blockIdx.x * blockDim.x + threadIdx.x;
    if (idx >= ROTCP * DHz) return;
    int f = idx % DHz;
    int n = idx / DHz;
    float v = 0.f;
    if (n < ROTC) {
        int h = n / 65, i = n % 65;
        v = rot[((size_t)f * NHASHz + h) * 65 + i];
    }
    g_rotT[(size_t)n * DHz + f] = v;
}

// ---------------- argmax over [rotated, -rotated] per (row,h) -> bucket key ----------------
__global__ void argmax_kernel() {
    int wid = (blockIdx.x * blockDim.x + threadIdx.x) >> 5;
    if (wid >= BHz * TPAD * NHASHz) return;
    int lane = threadIdx.x & 31;
    int h = wid % NHASHz;
    int row = wid / NHASHz;             // bh*TPAD + t
    const float* rp = g_ROT + (size_t)row * ROTCP + h * 65;
    float best = -3.402823e38f;
    int bidx = 0x7fffffff;
    for (int i = lane; i < 65; i += 32) {
        float dp = rp[i];
        if (dp > best || (dp == best && i < bidx)) { best = dp; bidx = i; }
        float nd = -dp; int ni = 65 + i;
        if (nd > best || (nd == best && ni < bidx)) { best = nd; bidx = ni; }
    }
    #pragma unroll
    for (int o = 16; o; o >>= 1) {
        float ov = __shfl_xor_sync(0xffffffffu, best, o);
        int oi = __shfl_xor_sync(0xffffffffu, bidx, o);
        if (ov > best || (ov == best && oi < bidx)) { best = ov; bidx = oi; }
    }
    if (lane == 0) {
        int bh = row / TPAD, t = row % TPAD;
        g_key[(size_t)bh * FLATz + h * TPAD + t] = (bidx + h * NBz) * TPAD + t;
    }
}

// ---------------- bitonic sort of 2080 (key, flat-index) pairs per bh ----------------
__global__ void __launch_bounds__(1024) sort_kernel() {
    int bh = blockIdx.x;
    __shared__ int sk[4096];
    __shared__ int sv[4096];
    int tid = threadIdx.x;
    for (int i = tid; i < 4096; i += 1024) {
        if (i < FLATz) { sk[i] = g_key[(size_t)bh * FLATz + i]; sv[i] = i; }
        else { sk[i] = 0x7fffffff; sv[i] = i; }
    }
    __syncthreads();
    for (int k = 2; k <= 4096; k <<= 1) {
        for (int j = k >> 1; j > 0; j >>= 1) {
            for (int i = tid; i < 4096; i += 1024) {
                int ixj = i ^ j;
                if (ixj > i) {
                    bool asc = ((i & k) == 0);
                    int a = sk[i], bb = sk[ixj];
                    if ((a > bb) == asc) {
                        sk[i] = bb; sk[ixj] = a;
                        int t = sv[i]; sv[i] = sv[ixj]; sv[ixj] = t;
                    }
                }
            }
            __syncthreads();
        }
    }
    for (int i = tid; i < FLATz; i += 1024) g_stick[(size_t)bh * FLATz + i] = sv[i];
}

// ---------------- find chunks containing token 515 (one per hash round per bh) ----------------
__global__ void find_sel_kernel() {
    int bh = blockIdx.x;
    const int* st = g_stick + (size_t)bh * FLATz;
    for (int i = threadIdx.x; i < FLATz; i += blockDim.x) {
        int f = st[i];
        if (f % TPAD == NTOK - 1) g_sel[bh * NHASHz + f / TPAD] = i >> 2;
    }
}

// ---------------- chunked LSH attention: one warp per (bh, chunk) [full, layer 1] ----------------
__global__ void chunk_attn_kernel() {
    int wid = (blockIdx.x * blockDim.x + threadIdx.x) >> 5;
    if (wid >= BHz * NCH) return;
    int lane = threadIdx.x & 31;
    int bh = wid / NCH, c = wid % NCH;
    int prev = (c == 0) ? (NCH - 1) : (c - 1);
    const int* st = g_stick + (size_t)bh * FLATz;

    int fq[4], tq[4], tk[8];
    #pragma unroll
    for (int i = 0; i < 4; i++) { fq[i] = st[c * 4 + i]; tq[i] = fq[i] % TPAD; }
    #pragma unroll
    for (int j = 0; j < 4; j++) tk[j] = tq[j];
    #pragma unroll
    for (int j = 0; j < 4; j++) { int f = st[prev * 4 + j]; tk[4 + j] = f % TPAD; }

    const float* QKb = g_QK + (size_t)bh * TPAD * DHz;
    const float* Vb  = g_V  + (size_t)bh * TPAD * DHz;
    int d0 = lane * 2;

    float2 q[4], k8[8], v8[8];
    #pragma unroll
    for (int i = 0; i < 4; i++) q[i] = *(const float2*)&QKb[(size_t)tq[i] * DHz + d0];
    #pragma unroll
    for (int j = 0; j < 8; j++) {
        k8[j] = *(const float2*)&QKb[(size_t)tk[j] * DHz + d0];
        v8[j] = *(const float2*)&Vb[(size_t)tk[j] * DHz + d0];
    }

    float ns[8];
    #pragma unroll
    for (int j = 0; j < 8; j++) ns[j] = k8[j].x * k8[j].x + k8[j].y * k8[j].y;
    #pragma unroll
    for (int o = 16; o; o >>= 1)
        #pragma unroll
        for (int j = 0; j < 8; j++) ns[j] += __shfl_xor_sync(0xffffffffu, ns[j], o);
    float rn[8];
    #pragma unroll
    for (int j = 0; j < 8; j++) rn[j] = 1.0f / sqrtf(fmaxf(ns[j], 1e-24f));

    float dt[4][8];
    #pragma unroll
    for (int i = 0; i < 4; i++)
        #pragma unroll
        for (int j = 0; j < 8; j++)
            dt[i][j] = q[i].x * k8[j].x + q[i].y * k8[j].y;
    #pragma unroll
    for (int o = 16; o; o >>= 1)
        #pragma unroll
        for (int i = 0; i < 4; i++)
            #pragma unroll
            for (int j = 0; j < 8; j++)
                dt[i][j] += __shfl_xor_sync(0xffffffffu, dt[i][j], o);

    #pragma unroll
    for (int i = 0; i < 4; i++)
        #pragma unroll
        for (int j = 0; j < 8; j++)
            dt[i][j] = (tq[i] == tk[j]) ? -5e4f : dt[i][j] * rn[j] * 0.125f;

    #pragma unroll
    for (int i = 0; i < 4; i++) {
        float mx = -3.402823e38f;
        #pragma unroll
        for (int j = 0; j < 8; j++) mx = fmaxf(mx, dt[i][j]);
        float p[8], se = 0.f;
        #pragma unroll
        for (int j = 0; j < 8; j++) { p[j] = expf(dt[i][j] - mx); se += p[j]; }
        float lse = logf(se) + mx;
        float inv = 1.0f / se;
        float2 o = make_float2(0.f, 0.f);
        #pragma unroll
        for (int j = 0; j < 8; j++) {
            float w = p[j] * inv;
            o.x += w * v8[j].x;
            o.y += w * v8[j].y;
        }
        int h = fq[i] / TPAD;
        size_t obase = (((size_t)(bh * NHASHz + h)) * TPAD + tq[i]);
        *(float2*)&g_O4[obase * DHz + d0] = o;
        if (lane == 0) g_LSE4[obase] = lse;
    }
}

// ---------------- layer-2 sparse chunk attention: only chunks containing token 515 ----------------
// V rows computed on the fly (same sequential-k FFMA order as the GEMM -> bit-identical).
__global__ void chunk_attn_sel_kernel(const float* __restrict__ Wv_l) {
    int wid = (blockIdx.x * blockDim.x + threadIdx.x) >> 5;
    if (wid >= BHz * NHASHz) return;
    int lane = threadIdx.x & 31;
    int bh = wid >> 2, slot = wid & 3;
    int c = g_sel[bh * NHASHz + slot];
    int prev = (c == 0) ? (NCH - 1) : (c - 1);
    const int* st = g_stick + (size_t)bh * FLATz;

    int fq[4], tq[4], tk[8];
    #pragma unroll
    for (int i = 0; i < 4; i++) { fq[i] = st[c * 4 + i]; tq[i] = fq[i] % TPAD; }
    #pragma unroll
    for (int j = 0; j < 4; j++) tk[j] = tq[j];
    #pragma unroll
    for (int j = 0; j < 4; j++) { int f = st[prev * 4 + j]; tk[4 + j] = f % TPAD; }

    const float* QKb = g_QK + (size_t)bh * TPAD * DHz;
    int d0 = lane * 2;
    int b = bh / Hz, head = bh % Hz;

    float2 q[4], k8[8];
    #pragma unroll
    for (int i = 0; i < 4; i++) q[i] = *(const float2*)&QKb[(size_t)tq[i] * DHz + d0];
    #pragma unroll
    for (int j = 0; j < 8; j++) k8[j] = *(const float2*)&QKb[(size_t)tk[j] * DHz + d0];

    // on-the-fly V: v8[j][d0..d0+1] = X[b][tk[j]][:] . Wv[head*64+d][:]
    float2 v8[8];
    {
        const float* w0 = Wv_l + (size_t)(head * DHz + d0) * Dz;
        const float* w1 = w0 + Dz;
        const float* xr[8];
        #pragma unroll
        for (int j = 0; j < 8; j++) xr[j] = g_X + ((size_t)b * TPAD + tk[j]) * Dz;
        float s0[8], s1[8];
        #pragma unroll
        for (int j = 0; j < 8; j++) { s0[j] = 0.f; s1[j] = 0.f; }
        for (int k = 0; k < Dz; k += 4) {
            float4 wa = *(const float4*)(w0 + k);
            float4 wb = *(const float4*)(w1 + k);
            #pragma unroll
            for (int j = 0; j < 8; j++) {
                float4 x = *(const float4*)(xr[j] + k);
                s0[j] += x.x * wa.x; s0[j] += x.y * wa.y; s0[j] += x.z * wa.z; s0[j] += x.w * wa.w;
                s1[j] += x.x * wb.x; s1[j] += x.y * wb.y; s1[j] += x.z * wb.z; s1[j] += x.w * wb.w;
            }
        }
        #pragma unroll
        for (int j = 0; j < 8; j++) { v8[j].x = s0[j]; v8[j].y = s1[j]; }
    }

    float ns[8];
    #pragma unroll
    for (int j = 0; j < 8; j++) ns[j] = k8[j].x * k8[j].x + k8[j].y * k8[j].y;
    #pragma unroll
    for (int o = 16; o; o >>= 1)
        #pragma unroll
        for (int j = 0; j < 8; j++) ns[j] += __shfl_xor_sync(0xffffffffu, ns[j], o);
    float rn[8];
    #pragma unroll
    for (int j = 0; j < 8; j++) rn[j] = 1.0f / sqrtf(fmaxf(ns[j], 1e-24f));

    float dt[4][8];
    #pragma unroll
    for (int i = 0; i < 4; i++)
        #pragma unroll
        for (int j = 0; j < 8; j++)
            dt[i][j] = q[i].x * k8[j].x + q[i].y * k8[j].y;
    #pragma unroll
    for (int o = 16; o; o >>= 1)
        #pragma unroll
        for (int i = 0; i < 4; i++)
            #pragma unroll
            for (int j = 0; j < 8; j++)
                dt[i][j] += __shfl_xor_sync(0xffffffffu, dt[i][j], o);

    #pragma unroll
    for (int i = 0; i < 4; i++)
        #pragma unroll
        for (int j = 0; j < 8; j++)
            dt[i][j] = (tq[i] == tk[j]) ? -5e4f : dt[i][j] * rn[j] * 0.125f;

    #pragma unroll
    for (int i = 0; i < 4; i++) {
        float mx = -3.402823e38f;
        #pragma unroll
        for (int j = 0; j < 8; j++) mx = fmaxf(mx, dt[i][j]);
        float p[8], se = 0.f;
        #pragma unroll
        for (int j = 0; j < 8; j++) { p[j] = expf(dt[i][j] - mx); se += p[j]; }
        float lse = logf(se) + mx;
        float inv = 1.0f / se;
        float2 o = make_float2(0.f, 0.f);
        #pragma unroll
        for (int j = 0; j < 8; j++) {
            float w = p[j] * inv;
            o.x += w * v8[j].x;
            o.y += w * v8[j].y;
        }
        int h = fq[i] / TPAD;
        size_t obase = (((size_t)(bh * NHASHz + h)) * TPAD + tq[i]);
        *(float2*)&g_O4[obase * DHz + d0] = o;
        if (lane == 0) g_LSE4[obase] = lse;
    }
}

// ---------------- combine hash rounds -> AO[b][t][h*64+dh] ----------------
// t_fixed < 0: all rows; else only that token row.
__global__ void combine_kernel(int t_fixed) {
    int gid = blockIdx.x * blockDim.x + threadIdx.x;
    int idx = gid >> 6;
    int d = gid & 63;
    int bh, t;
    if (t_fixed >= 0) {
        if (idx >= BHz) return;
        bh = idx; t = t_fixed;
    } else {
        if (idx >= BHz * TPAD) return;
        bh = idx / TPAD; t = idx % TPAD;
    }
    float l[NHASHz];
    float mx = -3.402823e38f;
    #pragma unroll
    for (int h = 0; h < NHASHz; h++) {
        l[h] = g_LSE4[((size_t)bh * NHASHz + h) * TPAD + t];
        mx = fmaxf(mx, l[h]);
    }
    float w[NHASHz], se = 0.f;
    #pragma unroll
    for (int h = 0; h < NHASHz; h++) { w[h] = expf(l[h] - mx); se += w[h]; }
    float inv = 1.0f / se;
    float o = 0.f;
    #pragma unroll
    for (int h = 0; h < NHASHz; h++)
        o += w[h] * inv * g_O4[(((size_t)bh * NHASHz + h) * TPAD + t) * DHz + d];
    int b = bh / Hz, head = bh % Hz;
    g_AO[((size_t)b * TPAD + t) * Dz + head * DHz + d] = o;
}

// ---------------- residual + LayerNorm, writes back into X ----------------
__global__ void ln_res_kernel(const float* __restrict__ g, const float* __restrict__ bb, int t_fixed) {
    int r = blockIdx.x;
    int b, t;
    if (t_fixed >= 0) { b = r; t = t_fixed; }
    else { b = r / NTOK; t = r % NTOK; }
    float* xr = g_X + ((size_t)b * TPAD + t) * Dz;
    const float* yr = g_Y + (size_t)r * Dz;
    int tid = threadIdx.x;
    float v0 = xr[tid] + yr[tid];
    float v1 = xr[tid + 256] + yr[tid + 256];
    float s = v0 + v1, ss = v0 * v0 + v1 * v1;
    __shared__ float shs[8], shss[8];
    __shared__ float s_mean, s_rstd;
    int lane = tid & 31, w = tid >> 5;
    #pragma unroll
    for (int o = 16; o; o >>= 1) {
        s += __shfl_xor_sync(0xffffffffu, s, o);
        ss += __shfl_xor_sync(0xffffffffu, ss, o);
    }
    if (lane == 0) { shs[w] = s; shss[w] = ss; }
    __syncthreads();
    if (tid == 0) {
        float S = 0.f, SS = 0.f;
        #pragma unroll
        for (int i = 0; i < 8; i++) { S += shs[i]; SS += shss[i]; }
        float m = S / Dz;
        float var = SS / Dz - m * m;
        s_mean = m;
        s_rstd = 1.0f / sqrtf(var + 1e-5f);
    }
    __syncthreads();
    float m = s_mean, rs = s_rstd;
    xr[tid]       = (v0 - m) * rs * g[tid]       + bb[tid];
    xr[tid + 256] = (v1 - m) * rs * g[tid + 256] + bb[tid + 256];
}

// ---------------- final LN(row 515) + projection -> dec[b] ----------------
__global__ void final_kernel(const float* __restrict__ gF, const float* __restrict__ bF,
                             const float* __restrict__ Wp, const float* __restrict__ bp) {
    int b = blockIdx.x;
    int tid = threadIdx.x;
    const float* xr = g_X + ((size_t)b * TPAD + (NTOK - 1)) * Dz;
    float v0 = xr[tid], v1 = xr[tid + 256];
    float s = v0 + v1, ss = v0 * v0 + v1 * v1;
    __shared__ float shs[8], shss[8], shp[8];
    __shared__ float s_mean, s_rstd;
    int lane = tid & 31, w = tid >> 5;
    #pragma unroll
    for (int o = 16; o; o >>= 1) {
        s += __shfl_xor_sync(0xffffffffu, s, o);
        ss += __shfl_xor_sync(0xffffffffu, ss, o);
    }
    if (lane == 0) { shs[w] = s; shss[w] = ss; }
    __syncthreads();
    if (tid == 0) {
        float S = 0.f, SS = 0.f;
        #pragma unroll
        for (int i = 0; i < 8; i++) { S += shs[i]; SS += shss[i]; }
        float m = S / Dz;
        float var = SS / Dz - m * m;
        s_mean = m;
        s_rstd = 1.0f / sqrtf(var + 1e-5f);
    }
    __syncthreads();
    float m = s_mean, rs = s_rstd;
    float y0 = (v0 - m) * rs * gF[tid] + bF[tid];
    float y1 = (v1 - m) * rs * gF[tid + 256] + bF[tid + 256];
    float p = y0 * Wp[tid] + y1 * Wp[tid + 256];
    #pragma unroll
    for (int o = 16; o; o >>= 1) p += __shfl_xor_sync(0xffffffffu, p, o);
    if (lane == 0) shp[w] = p;
    __syncthreads();
    if (tid == 0) {
        float P = 0.f;
        #pragma unroll
        for (int i = 0; i < 8; i++) P += shp[i];
        g_dec[b] = P + bp[0];
    }
}

// ---------------- broadcast output: out[i][j][e] = dec[j]*std[i,e] + mean[i,e] ----------------
__global__ void out_kernel(float* __restrict__ out) {
    int idx = blockIdx.x * blockDim.x + threadIdx.x;
    if (idx >= Bz * Bz * Ez) return;
    int e = idx % Ez;
    int j = (idx / Ez) % Bz;
    int i = idx / (Ez * Bz);
    out[idx] = g_dec[j] * g_std[i * Ez + e] + g_mean[i * Ez + e];
}

// ================================================================================
extern "C" void kernel_launch(void* const* d_in, const int* in_sizes, int n_in,
                              void* d_out, int out_size) {
    const float* x_enc  = (const float*)d_in[0];
    const float* x_mark = (const float*)d_in[1];
    const float* W_emb  = (const float*)d_in[2];
    const float* b_emb  = (const float*)d_in[3];
    const float* Wqk    = (const float*)d_in[4];
    const float* Wv     = (const float*)d_in[5];
    const float* Wo     = (const float*)d_in[6];
    const float* bo     = (const float*)d_in[7];
    const float* Wc1    = (const float*)d_in[8];
    const float* bc1    = (const float*)d_in[9];
    const float* Wc2    = (const float*)d_in[10];
    const float* bc2    = (const float*)d_in[11];
    const float* g1     = (const float*)d_in[12];
    const float* b1     = (const float*)d_in[13];
    const float* g2     = (const float*)d_in[14];
    const float* b2     = (const float*)d_in[15];
    const float* gF     = (const float*)d_in[16];
    const float* bF     = (const float*)d_in[17];
    const float* Wp     = (const float*)d_in[18];
    const float* bp     = (const float*)d_in[19];
    const float* rot    = (const float*)d_in[20];
    float* out = (float*)d_out;

    float *p_tok, *p_X, *p_QK, *p_V, *p_rotT, *p_ROT, *p_AO, *p_Y, *p_H1;
    cudaGetSymbolAddress((void**)&p_tok,  g_tok);
    cudaGetSymbolAddress((void**)&p_X,    g_X);
    cudaGetSymbolAddress((void**)&p_QK,   g_QK);
    cudaGetSymbolAddress((void**)&p_V,    g_V);
    cudaGetSymbolAddress((void**)&p_rotT, g_rotT);
    cudaGetSymbolAddress((void**)&p_ROT,  g_ROT);
    cudaGetSymbolAddress((void**)&p_AO,   g_AO);
    cudaGetSymbolAddress((void**)&p_Y,    g_Y);
    cudaGetSymbolAddress((void**)&p_H1,   g_H1);

    // ---- RevIN + tokenization + embedding ----
    stats_kernel<<<2048, 256>>>(x_enc);
    tok_kernel<<<(Bz * NTOK * Lz + 255) / 256, 256>>>(x_enc, x_mark);
    zero_pad_kernel<<<(Bz * 4 * Dz + 255) / 256, 256>>>();
    // X[:, :516, :] = TOK @ W_emb^T + b_emb
    gemm128<<<dim3(Dz / 128, (Bz * NTOK + 127) / 128), 256>>>(
        p_tok, W_emb, b_emb, p_X, Bz * NTOK, Dz, Lz,
        0, 0, -1, 1, NTOK, TPAD, 0);

    for (int l = 0; l < 2; l++) {
        const float* Wqk_l = Wqk + (size_t)l * Dz * Dz;
        const float* Wv_l  = Wv  + (size_t)l * Dz * Dz;
        const float* Wo_l  = Wo  + (size_t)l * Dz * Dz;
        const float* bo_l  = bo  + (size_t)l * Dz;
        const float* Wc1_l = Wc1 + (size_t)l * DFFz * Dz;
        const float* bc1_l = bc1 + (size_t)l * DFFz;
        const float* Wc2_l = Wc2 + (size_t)l * Dz * DFFz;
        const float* bc2_l = bc2 + (size_t)l * Dz;
        const float* g1_l = g1 + (size_t)l * Dz;
        const float* b1_l = b1 + (size_t)l * Dz;
        const float* g2_l = g2 + (size_t)l * Dz;
        const float* b2_l = b2 + (size_t)l * Dz;
        const float* rot_l = rot + (size_t)l * DHz * NHASHz * (NBz / 2);

        // QK projection (head-split output [bh, t, dh])
        gemm128<<<dim3(Dz / 128, (Bz * TPAD) / 128), 256>>>(
            p_X, Wqk_l, nullptr, p_QK, Bz * TPAD, Dz, Dz,
            0, 0, -1, 2, 0, TPAD, 0);
        if (l == 0) {
            gemm128<<<dim3(Dz / 128, (Bz * TPAD) / 128), 256>>>(
                p_X, Wv_l, nullptr, p_V, Bz * TPAD, Dz, Dz,
                0, 0, -1, 2, 0, TPAD, 0);
        }

        // LSH bucketing: rotated = QK @ rotT^T, then argmax -> sort keys
        rotT_kernel<<<(ROTCP * DHz + 255) / 256, 256>>>(rot_l);
        gemm128<<<dim3(ROTCP / 128, (BHz * TPAD) / 128), 256>>>(
            p_QK, p_rotT, nullptr, p_ROT, BHz * TPAD, ROTCP, DHz,
            0, 0, -1, 0, 0, 0, 0);
        argmax_kernel<<<(BHz * TPAD * NHASHz * 32 + 255) / 256, 256>>>();
        sort_kernel<<<BHz, 1024>>>();

        if (l == 0) {
            chunk_attn_kernel<<<(BHz * NCH) / 4, 128>>>();
            combine_kernel<<<(BHz * TPAD * 64) / 256, 256>>>(-1);

            gemm128<<<dim3(Dz / 128, (Bz * NTOK + 127) / 128), 256>>>(
                p_AO, Wo_l, bo_l, p_Y, Bz * NTOK, Dz, Dz,
                NTOK, TPAD, -1, 0, 0, 0, 0);
            ln_res_kernel<<<Bz * NTOK, 256>>>(g1_l, b1_l, -1);
            gemm128<<<dim3(DFFz / 128, (Bz * NTOK + 127) / 128), 256>>>(
                p_X, Wc1_l, bc1_l, p_H1, Bz * NTOK, DFFz, Dz,
                NTOK, TPAD, -1, 0, 0, 0, 1);
            gemm128<<<dim3(Dz / 128, (Bz * NTOK + 127) / 128), 256>>>(
                p_H1, Wc2_l, bc2_l, p_Y, Bz * NTOK, Dz, DFFz,
                0, 0, -1, 0, 0, 0, 0);
            ln_res_kernel<<<Bz * NTOK, 256>>>(g2_l, b2_l, -1);
        } else {
            // last layer: only token 515 feeds the output head.
            // sparse attention: only the 4 chunks (per bh) containing token 515,
            // V rows computed on the fly (V GEMM skipped entirely).
            find_sel_kernel<<<BHz, 256>>>();
            chunk_attn_sel_kernel<<<(BHz * NHASHz * 32 + 127) / 128, 128>>>(Wv_l);
            combine_kernel<<<(BHz * 64) / 256, 256>>>(NTOK - 1);

            gemm128<<<dim3(Dz / 128, 1), 256>>>(
                p_AO, Wo_l, bo_l, p_Y, Bz, Dz, Dz,
                0, TPAD, NTOK - 1, 0, 0, 0, 0);
            ln_res_kernel<<<Bz, 256>>>(g1_l, b1_l, NTOK - 1);
            gemm128<<<dim3(DFFz / 128, 1), 256>>>(
                p_X, Wc1_l, bc1_l, p_H1, Bz, DFFz, Dz,
                0, TPAD, NTOK - 1, 0, 0, 0, 1);
            gemm128<<<dim3(Dz / 128, 1), 256>>>(
                p_H1, Wc2_l, bc2_l, p_Y, Bz, Dz, DFFz,
                0, 0, -1, 0, 0, 0, 0);
            ln_res_kernel<<<Bz, 256>>>(g2_l, b2_l, NTOK - 1);
        }
    }

    final_kernel<<<Bz, 256>>>(gF, bF, Wp, bp);
    out_kernel<<<(Bz * Bz * Ez + 255) / 256, 256>>>(out);
}

// round 3
// speedup vs baseline: 1.2581x; 1.0026x over previous
#include <cuda_runtime.h>
#include <math.h>

#define Bz 32
#define Lz 512
#define Ez 512
#define NMARKz 4
#define Dz 512
#define Hz 8
#define DFFz 2048
#define NHASHz 4
#define NTOK 516
#define TPAD 520
#define DHz 64
#define NBz 130
#define NCH 520
#define BHz 256          // B*H
#define FLATz 2080       // NHASH*TPAD
#define ROTC 260         // NHASH*65
#define ROTCP 384        // padded to multiple of 128

// ---------------- scratch (static device globals; no allocation) ----------------
static __device__ float g_mean[Bz * Ez];
static __device__ float g_std[Bz * Ez];
static __device__ float g_tok[(size_t)Bz * NTOK * Lz];
static __device__ float g_X[(size_t)Bz * TPAD * Dz];
static __device__ float g_QK[(size_t)BHz * TPAD * DHz];
static __device__ float g_V[(size_t)BHz * TPAD * DHz];
static __device__ float g_rotT[ROTCP * DHz];
static __device__ float g_ROT[(size_t)BHz * TPAD * ROTCP];
static __device__ int   g_key[(size_t)BHz * FLATz];
static __device__ int   g_stick[(size_t)BHz * FLATz];
static __device__ int   g_sel[BHz * NHASHz];
static __device__ float g_O4[(size_t)BHz * NHASHz * TPAD * DHz];
static __device__ float g_LSE4[(size_t)BHz * NHASHz * TPAD];
static __device__ float g_AO[(size_t)Bz * TPAD * Dz];
static __device__ float g_Y[(size_t)Bz * NTOK * Dz];
static __device__ float g_H1[(size_t)Bz * NTOK * DFFz];
static __device__ float g_dec[Bz];

// ---------------- RevIN stats: mean/std per (b,e) over L ----------------
__global__ void stats_kernel(const float* __restrict__ x) {
    int w = (blockIdx.x * blockDim.x + threadIdx.x) >> 5;
    int lane = threadIdx.x & 31;
    if (w >= Bz * Ez) return;
    int b = w / Ez, e = w % Ez;
    const float* p = x + (size_t)b * Lz * Ez + e;
    float s = 0.f, ss = 0.f;
    for (int l = lane; l < Lz; l += 32) {
        float v = p[(size_t)l * Ez];
        s += v; ss += v * v;
    }
    #pragma unroll
    for (int o = 16; o; o >>= 1) {
        s += __shfl_xor_sync(0xffffffffu, s, o);
        ss += __shfl_xor_sync(0xffffffffu, ss, o);
    }
    if (lane == 0) {
        float m = s / Lz;
        float var = ss / Lz - m * m;
        g_mean[w] = m;
        g_std[w] = sqrtf(var + 1e-5f);
    }
}

// ---------------- build inverted tokens: TOK[b][n][l] ----------------
__global__ void tok_kernel(const float* __restrict__ x_enc, const float* __restrict__ x_mark) {
    int idx = blockIdx.x * blockDim.x + threadIdx.x;
    if (idx >= Bz * NTOK * Lz) return;
    int l = idx % Lz;
    int n = (idx / Lz) % NTOK;
    int b = idx / (Lz * NTOK);
    float v;
    if (n < Ez) {
        v = (x_enc[((size_t)b * Lz + l) * Ez + n] - g_mean[b * Ez + n]) / g_std[b * Ez + n];
    } else {
        v = x_mark[((size_t)b * Lz + l) * NMARKz + (n - Ez)];
    }
    g_tok[idx] = v;
}

// ---------------- zero padding rows of X (516..519 per batch) ----------------
__global__ void zero_pad_kernel() {
    int idx = blockIdx.x * blockDim.x + threadIdx.x;
    if (idx >= Bz * 4 * Dz) return;
    int d = idx % Dz;
    int t = (idx / Dz) % 4;
    int b = idx / (Dz * 4);
    g_X[((size_t)b * TPAD + NTOK + t) * Dz + d] = 0.f;
}

// ---------------- 128x128x8 tiled GEMM: C = A @ W^T (+bias)(+relu) ----------------
// A row remap: a_fixed_t>=0 -> row m uses A + (m*a_pitch + a_fixed_t)*K
//              else a_seg_len>0 -> b=m/a_seg_len,r=m%a_seg_len -> (b*a_pitch+r)*K
//              else plain m*K.
// C modes: 0 plain [M,N]; 1 seg remap (b*c_pitch + r)*N; 2 head split [b,h,t,dh]
__global__ void __launch_bounds__(256, 2) gemm128(
    const float* __restrict__ A, const float* __restrict__ W,
    const float* __restrict__ bias, float* __restrict__ C,
    int M, int N, int K,
    int a_seg_len, int a_pitch, int a_fixed_t,
    int c_mode, int c_seg, int c_pitch, int relu)
{
    __shared__ float As[2][8][128];
    __shared__ float Bs[2][8][128];
    const int tid = threadIdx.x;
    const int m0 = blockIdx.y * 128, n0 = blockIdx.x * 128;
    const int tx = tid & 15, ty = tid >> 4;
    float acc[8][8];
    #pragma unroll
    for (int i = 0; i < 8; i++)
        #pragma unroll
        for (int j = 0; j < 8; j++) acc[i][j] = 0.f;

    const int lr = tid >> 1;          // 0..127
    const int lk = (tid & 1) * 4;     // 0 or 4
    const int am = m0 + lr;
    const float* arow = nullptr;
    if (am < M) {
        if (a_fixed_t >= 0) arow = A + ((size_t)am * a_pitch + a_fixed_t) * (size_t)K;
        else if (a_seg_len > 0) arow = A + ((size_t)(am / a_seg_len) * a_pitch + (am % a_seg_len)) * (size_t)K;
        else arow = A + (size_t)am * K;
    }
    const float* wrow = W + (size_t)(n0 + lr) * K;

    // prologue: load tile 0
    float4 av = arow ? *(const float4*)(arow + lk) : make_float4(0.f, 0.f, 0.f, 0.f);
    float4 wv = *(const float4*)(wrow + lk);
    As[0][lk + 0][lr] = av.x; As[0][lk + 1][lr] = av.y; As[0][lk + 2][lr] = av.z; As[0][lk + 3][lr] = av.w;
    Bs[0][lk + 0][lr] = wv.x; Bs[0][lk + 1][lr] = wv.y; Bs[0][lk + 2][lr] = wv.z; Bs[0][lk + 3][lr] = wv.w;
    __syncthreads();

    int buf = 0;
    for (int k0 = 0; k0 < K; k0 += 8) {
        const bool more = (k0 + 8 < K);
        float4 av2, wv2;
        if (more) {
            av2 = arow ? *(const float4*)(arow + k0 + 8 + lk) : make_float4(0.f, 0.f, 0.f, 0.f);
            wv2 = *(const float4*)(wrow + k0 + 8 + lk);
        }
        #pragma unroll
        for (int k = 0; k < 8; k++) {
            float4 a0 = *(const float4*)&As[buf][k][ty * 8];
            float4 a1 = *(const float4*)&As[buf][k][ty * 8 + 4];
            float4 b0 = *(const float4*)&Bs[buf][k][tx * 8];
            float4 b1 = *(const float4*)&Bs[buf][k][tx * 8 + 4];
            float a[8] = {a0.x, a0.y, a0.z, a0.w, a1.x, a1.y, a1.z, a1.w};
            float b[8] = {b0.x, b0.y, b0.z, b0.w, b1.x, b1.y, b1.z, b1.w};
            #pragma unroll
            for (int i = 0; i < 8; i++)
                #pragma unroll
                for (int j = 0; j < 8; j++)
                    acc[i][j] += a[i] * b[j];
        }
        if (more) {
            int nb = buf ^ 1;
            As[nb][lk + 0][lr] = av2.x; As[nb][lk + 1][lr] = av2.y; As[nb][lk + 2][lr] = av2.z; As[nb][lk + 3][lr] = av2.w;
            Bs[nb][lk + 0][lr] = wv2.x; Bs[nb][lk + 1][lr] = wv2.y; Bs[nb][lk + 2][lr] = wv2.z; Bs[nb][lk + 3][lr] = wv2.w;
            __syncthreads();
            buf = nb;
        }
    }

    // epilogue
    const int gn0 = n0 + tx * 8;
    float bb[8];
    #pragma unroll
    for (int j = 0; j < 8; j++) bb[j] = bias ? bias[gn0 + j] : 0.f;

    #pragma unroll
    for (int i = 0; i < 8; i++) {
        int gm = m0 + ty * 8 + i;
        if (gm >= M) continue;
        size_t base;
        if (c_mode == 2) {
            int b = gm / c_pitch, t = gm % c_pitch;
            int head = gn0 >> 6;
            base = (((size_t)(b * Hz + head)) * c_pitch + t) * DHz + (gn0 & 63);
        } else if (c_mode == 1) {
            int b = gm / c_seg, r = gm % c_seg;
            base = ((size_t)b * c_pitch + r) * (size_t)N + gn0;
        } else {
            base = (size_t)gm * N + gn0;
        }
        #pragma unroll
        for (int jj = 0; jj < 8; jj += 4) {
            float4 v;
            v.x = acc[i][jj + 0] + bb[jj + 0];
            v.y = acc[i][jj + 1] + bb[jj + 1];
            v.z = acc[i][jj + 2] + bb[jj + 2];
            v.w = acc[i][jj + 3] + bb[jj + 3];
            if (relu) {
                v.x = fmaxf(v.x, 0.f); v.y = fmaxf(v.y, 0.f);
                v.z = fmaxf(v.z, 0.f); v.w = fmaxf(v.w, 0.f);
            }
            *(float4*)&C[base + jj] = v;
        }
    }
}

// ---------------- transpose rot[f][h][i] -> rotT[n=h*65+i][f] (zero-pad to 384) ----------------
__global__ void rotT_kernel(const float* __restrict__ rot) {
    int idx = blockIdx.x * blockDim.x + threadIdx.x;
    if (idx >= ROTCP * DHz) return;
    int f = idx % DHz;
    int n = idx / DHz;
    float v = 0.f;
    if (n < ROTC) {
        int h = n / 65, i = n % 65;
        v = rot[((size_t)f * NHASHz + h) * 65 + i];
    }
    g_rotT[(size_t)n * DHz + f] = v;
}

// ---------------- argmax over [rotated, -rotated] per (row,h) -> bucket key ----------------
__global__ void argmax_kernel() {
    int wid = (blockIdx.x * blockDim.x + threadIdx.x) >> 5;
    if (wid >= BHz * TPAD * NHASHz) return;
    int lane = threadIdx.x & 31;
    int h = wid % NHASHz;
    int row = wid / NHASHz;             // bh*TPAD + t
    const float* rp = g_ROT + (size_t)row * ROTCP + h * 65;
    float best = -3.402823e38f;
    int bidx = 0x7fffffff;
    for (int i = lane; i < 65; i += 32) {
        float dp = rp[i];
        if (dp > best || (dp == best && i < bidx)) { best = dp; bidx = i; }
        float nd = -dp; int ni = 65 + i;
        if (nd > best || (nd == best && ni < bidx)) { best = nd; bidx = ni; }
    }
    #pragma unroll
    for (int o = 16; o; o >>= 1) {
        float ov = __shfl_xor_sync(0xffffffffu, best, o);
        int oi = __shfl_xor_sync(0xffffffffu, bidx, o);
        if (ov > best || (ov == best && oi < bidx)) { best = ov; bidx = oi; }
    }
    if (lane == 0) {
        int bh = row / TPAD, t = row % TPAD;
        g_key[(size_t)bh * FLATz + h * TPAD + t] = (bidx + h * NBz) * TPAD + t;
    }
}

// ---------------- bitonic sort of 2080 (key, flat-index) pairs per bh ----------------
__global__ void __launch_bounds__(1024) sort_kernel() {
    int bh = blockIdx.x;
    __shared__ int sk[4096];
    __shared__ int sv[4096];
    int tid = threadIdx.x;
    for (int i = tid; i < 4096; i += 1024) {
        if (i < FLATz) { sk[i] = g_key[(size_t)bh * FLATz + i]; sv[i] = i; }
        else { sk[i] = 0x7fffffff; sv[i] = i; }
    }
    __syncthreads();
    for (int k = 2; k <= 4096; k <<= 1) {
        for (int j = k >> 1; j > 0; j >>= 1) {
            for (int i = tid; i < 4096; i += 1024) {
                int ixj = i ^ j;
                if (ixj > i) {
                    bool asc = ((i & k) == 0);
                    int a = sk[i], bb = sk[ixj];
                    if ((a > bb) == asc) {
                        sk[i] = bb; sk[ixj] = a;
                        int t = sv[i]; sv[i] = sv[ixj]; sv[ixj] = t;
                    }
                }
            }
            __syncthreads();
        }
    }
    for (int i = tid; i < FLATz; i += 1024) g_stick[(size_t)bh * FLATz + i] = sv[i];
}

// ---------------- find chunks containing token 515 (one per hash round per bh) ----------------
__global__ void find_sel_kernel() {
    int bh = blockIdx.x;
    const int* st = g_stick + (size_t)bh * FLATz;
    for (int i = threadIdx.x; i < FLATz; i += blockDim.x) {
        int f = st[i];
        if (f % TPAD == NTOK - 1) g_sel[bh * NHASHz + f / TPAD] = i >> 2;
    }
}

// ---------------- chunked LSH attention: one warp per (bh, chunk) [full, layer 1] ----------------
__global__ void chunk_attn_kernel() {
    int wid = (blockIdx.x * blockDim.x + threadIdx.x) >> 5;
    if (wid >= BHz * NCH) return;
    int lane = threadIdx.x & 31;
    int bh = wid / NCH, c = wid % NCH;
    int prev = (c == 0) ? (NCH - 1) : (c - 1);
    const int* st = g_stick + (size_t)bh * FLATz;

    int fq[4], tq[4], tk[8];
    #pragma unroll
    for (int i = 0; i < 4; i++) { fq[i] = st[c * 4 + i]; tq[i] = fq[i] % TPAD; }
    #pragma unroll
    for (int j = 0; j < 4; j++) tk[j] = tq[j];
    #pragma unroll
    for (int j = 0; j < 4; j++) { int f = st[prev * 4 + j]; tk[4 + j] = f % TPAD; }

    const float* QKb = g_QK + (size_t)bh * TPAD * DHz;
    const float* Vb  = g_V  + (size_t)bh * TPAD * DHz;
    int d0 = lane * 2;

    float2 q[4], k8[8], v8[8];
    #pragma unroll
    for (int i = 0; i < 4; i++) q[i] = *(const float2*)&QKb[(size_t)tq[i] * DHz + d0];
    #pragma unroll
    for (int j = 0; j < 8; j++) {
        k8[j] = *(const float2*)&QKb[(size_t)tk[j] * DHz + d0];
        v8[j] = *(const float2*)&Vb[(size_t)tk[j] * DHz + d0];
    }

    float ns[8];
    #pragma unroll
    for (int j = 0; j < 8; j++) ns[j] = k8[j].x * k8[j].x + k8[j].y * k8[j].y;
    #pragma unroll
    for (int o = 16; o; o >>= 1)
        #pragma unroll
        for (int j = 0; j < 8; j++) ns[j] += __shfl_xor_sync(0xffffffffu, ns[j], o);
    float rn[8];
    #pragma unroll
    for (int j = 0; j < 8; j++) rn[j] = 1.0f / sqrtf(fmaxf(ns[j], 1e-24f));

    float dt[4][8];
    #pragma unroll
    for (int i = 0; i < 4; i++)
        #pragma unroll
        for (int j = 0; j < 8; j++)
            dt[i][j] = q[i].x * k8[j].x + q[i].y * k8[j].y;
    #pragma unroll
    for (int o = 16; o; o >>= 1)
        #pragma unroll
        for (int i = 0; i < 4; i++)
            #pragma unroll
            for (int j = 0; j < 8; j++)
                dt[i][j] += __shfl_xor_sync(0xffffffffu, dt[i][j], o);

    #pragma unroll
    for (int i = 0; i < 4; i++)
        #pragma unroll
        for (int j = 0; j < 8; j++)
            dt[i][j] = (tq[i] == tk[j]) ? -5e4f : dt[i][j] * rn[j] * 0.125f;

    #pragma unroll
    for (int i = 0; i < 4; i++) {
        float mx = -3.402823e38f;
        #pragma unroll
        for (int j = 0; j < 8; j++) mx = fmaxf(mx, dt[i][j]);
        float p[8], se = 0.f;
        #pragma unroll
        for (int j = 0; j < 8; j++) { p[j] = expf(dt[i][j] - mx); se += p[j]; }
        float lse = logf(se) + mx;
        float inv = 1.0f / se;
        float2 o = make_float2(0.f, 0.f);
        #pragma unroll
        for (int j = 0; j < 8; j++) {
            float w = p[j] * inv;
            o.x += w * v8[j].x;
            o.y += w * v8[j].y;
        }
        int h = fq[i] / TPAD;
        size_t obase = (((size_t)(bh * NHASHz + h)) * TPAD + tq[i]);
        *(float2*)&g_O4[obase * DHz + d0] = o;
        if (lane == 0) g_LSE4[obase] = lse;
    }
}

// ---------------- layer-2 sparse chunk attention: only chunks containing token 515 ----------------
// V rows computed on the fly (same sequential-k FFMA order as the GEMM -> bit-identical).
__global__ void chunk_attn_sel_kernel(const float* __restrict__ Wv_l) {
    int wid = (blockIdx.x * blockDim.x + threadIdx.x) >> 5;
    if (wid >= BHz * NHASHz) return;
    int lane = threadIdx.x & 31;
    int bh = wid >> 2, slot = wid & 3;
    int c = g_sel[bh * NHASHz + slot];
    int prev = (c == 0) ? (NCH - 1) : (c - 1);
    const int* st = g_stick + (size_t)bh * FLATz;

    int fq[4], tq[4], tk[8];
    #pragma unroll
    for (int i = 0; i < 4; i++) { fq[i] = st[c * 4 + i]; tq[i] = fq[i] % TPAD; }
    #pragma unroll
    for (int j = 0; j < 4; j++) tk[j] = tq[j];
    #pragma unroll
    for (int j = 0; j < 4; j++) { int f = st[prev * 4 + j]; tk[4 + j] = f % TPAD; }

    const float* QKb = g_QK + (size_t)bh * TPAD * DHz;
    int d0 = lane * 2;
    int b = bh / Hz, head = bh % Hz;

    float2 q[4], k8[8];
    #pragma unroll
    for (int i = 0; i < 4; i++) q[i] = *(const float2*)&QKb[(size_t)tq[i] * DHz + d0];
    #pragma unroll
    for (int j = 0; j < 8; j++) k8[j] = *(const float2*)&QKb[(size_t)tk[j] * DHz + d0];

    // on-the-fly V: v8[j][d0..d0+1] = X[b][tk[j]][:] . Wv[head*64+d][:]
    float2 v8[8];
    {
        const float* w0 = Wv_l + (size_t)(head * DHz + d0) * Dz;
        const float* w1 = w0 + Dz;
        const float* xr[8];
        #pragma unroll
        for (int j = 0; j < 8; j++) xr[j] = g_X + ((size_t)b * TPAD + tk[j]) * Dz;
        float s0[8], s1[8];
        #pragma unroll
        for (int j = 0; j < 8; j++) { s0[j] = 0.f; s1[j] = 0.f; }
        for (int k = 0; k < Dz; k += 4) {
            float4 wa = *(const float4*)(w0 + k);
            float4 wb = *(const float4*)(w1 + k);
            #pragma unroll
            for (int j = 0; j < 8; j++) {
                float4 x = *(const float4*)(xr[j] + k);
                s0[j] += x.x * wa.x; s0[j] += x.y * wa.y; s0[j] += x.z * wa.z; s0[j] += x.w * wa.w;
                s1[j] += x.x * wb.x; s1[j] += x.y * wb.y; s1[j] += x.z * wb.z; s1[j] += x.w * wb.w;
            }
        }
        #pragma unroll
        for (int j = 0; j < 8; j++) { v8[j].x = s0[j]; v8[j].y = s1[j]; }
    }

    float ns[8];
    #pragma unroll
    for (int j = 0; j < 8; j++) ns[j] = k8[j].x * k8[j].x + k8[j].y * k8[j].y;
    #pragma unroll
    for (int o = 16; o; o >>= 1)
        #pragma unroll
        for (int j = 0; j < 8; j++) ns[j] += __shfl_xor_sync(0xffffffffu, ns[j], o);
    float rn[8];
    #pragma unroll
    for (int j = 0; j < 8; j++) rn[j] = 1.0f / sqrtf(fmaxf(ns[j], 1e-24f));

    float dt[4][8];
    #pragma unroll
    for (int i = 0; i < 4; i++)
        #pragma unroll
        for (int j = 0; j < 8; j++)
            dt[i][j] = q[i].x * k8[j].x + q[i].y * k8[j].y;
    #pragma unroll
    for (int o = 16; o; o >>= 1)
        #pragma unroll
        for (int i = 0; i < 4; i++)
            #pragma unroll
            for (int j = 0; j < 8; j++)
                dt[i][j] += __shfl_xor_sync(0xffffffffu, dt[i][j], o);

    #pragma unroll
    for (int i = 0; i < 4; i++)
        #pragma unroll
        for (int j = 0; j < 8; j++)
            dt[i][j] = (tq[i] == tk[j]) ? -5e4f : dt[i][j] * rn[j] * 0.125f;

    #pragma unroll
    for (int i = 0; i < 4; i++) {
        float mx = -3.402823e38f;
        #pragma unroll
        for (int j = 0; j < 8; j++) mx = fmaxf(mx, dt[i][j]);
        float p[8], se = 0.f;
        #pragma unroll
        for (int j = 0; j < 8; j++) { p[j] = expf(dt[i][j] - mx); se += p[j]; }
        float lse = logf(se) + mx;
        float inv = 1.0f / se;
        float2 o = make_float2(0.f, 0.f);
        #pragma unroll
        for (int j = 0; j < 8; j++) {
            float w = p[j] * inv;
            o.x += w * v8[j].x;
            o.y += w * v8[j].y;
        }
        int h = fq[i] / TPAD;
        size_t obase = (((size_t)(bh * NHASHz + h)) * TPAD + tq[i]);
        *(float2*)&g_O4[obase * DHz + d0] = o;
        if (lane == 0) g_LSE4[obase] = lse;
    }
}

// ---------------- combine hash rounds -> AO[b][t][h*64+dh] ----------------
// t_fixed < 0: all rows; else only that token row.
__global__ void combine_kernel(int t_fixed) {
    int gid = blockIdx.x * blockDim.x + threadIdx.x;
    int idx = gid >> 6;
    int d = gid & 63;
    int bh, t;
    if (t_fixed >= 0) {
        if (idx >= BHz) return;
        bh = idx; t = t_fixed;
    } else {
        if (idx >= BHz * TPAD) return;
        bh = idx / TPAD; t = idx % TPAD;
    }
    float l[NHASHz];
    float mx = -3.402823e38f;
    #pragma unroll
    for (int h = 0; h < NHASHz; h++) {
        l[h] = g_LSE4[((size_t)bh * NHASHz + h) * TPAD + t];
        mx = fmaxf(mx, l[h]);
    }
    float w[NHASHz], se = 0.f;
    #pragma unroll
    for (int h = 0; h < NHASHz; h++) { w[h] = expf(l[h] - mx); se += w[h]; }
    float inv = 1.0f / se;
    float o = 0.f;
    #pragma unroll
    for (int h = 0; h < NHASHz; h++)
        o += w[h] * inv * g_O4[(((size_t)bh * NHASHz + h) * TPAD + t) * DHz + d];
    int b = bh / Hz, head = bh % Hz;
    g_AO[((size_t)b * TPAD + t) * Dz + head * DHz + d] = o;
}

// ---------------- residual + LayerNorm, writes back into X ----------------
__global__ void ln_res_kernel(const float* __restrict__ g, const float* __restrict__ bb, int t_fixed) {
    int r = blockIdx.x;
    int b, t;
    if (t_fixed >= 0) { b = r; t = t_fixed; }
    else { b = r / NTOK; t = r % NTOK; }
    float* xr = g_X + ((size_t)b * TPAD + t) * Dz;
    const float* yr = g_Y + (size_t)r * Dz;
    int tid = threadIdx.x;
    float v0 = xr[tid] + yr[tid];
    float v1 = xr[tid + 256] + yr[tid + 256];
    float s = v0 + v1, ss = v0 * v0 + v1 * v1;
    __shared__ float shs[8], shss[8];
    __shared__ float s_mean, s_rstd;
    int lane = tid & 31, w = tid >> 5;
    #pragma unroll
    for (int o = 16; o; o >>= 1) {
        s += __shfl_xor_sync(0xffffffffu, s, o);
        ss += __shfl_xor_sync(0xffffffffu, ss, o);
    }
    if (lane == 0) { shs[w] = s; shss[w] = ss; }
    __syncthreads();
    if (tid == 0) {
        float S = 0.f, SS = 0.f;
        #pragma unroll
        for (int i = 0; i < 8; i++) { S += shs[i]; SS += shss[i]; }
        float m = S / Dz;
        float var = SS / Dz - m * m;
        s_mean = m;
        s_rstd = 1.0f / sqrtf(var + 1e-5f);
    }
    __syncthreads();
    float m = s_mean, rs = s_rstd;
    xr[tid]       = (v0 - m) * rs * g[tid]       + bb[tid];
    xr[tid + 256] = (v1 - m) * rs * g[tid + 256] + bb[tid + 256];
}

// ---------------- final LN(row 515) + projection -> dec[b] ----------------
__global__ void final_kernel(const float* __restrict__ gF, const float* __restrict__ bF,
                             const float* __restrict__ Wp, const float* __restrict__ bp) {
    int b = blockIdx.x;
    int tid = threadIdx.x;
    const float* xr = g_X + ((size_t)b * TPAD + (NTOK - 1)) * Dz;
    float v0 = xr[tid], v1 = xr[tid + 256];
    float s = v0 + v1, ss = v0 * v0 + v1 * v1;
    __shared__ float shs[8], shss[8], shp[8];
    __shared__ float s_mean, s_rstd;
    int lane = tid & 31, w = tid >> 5;
    #pragma unroll
    for (int o = 16; o; o >>= 1) {
        s += __shfl_xor_sync(0xffffffffu, s, o);
        ss += __shfl_xor_sync(0xffffffffu, ss, o);
    }
    if (lane == 0) { shs[w] = s; shss[w] = ss; }
    __syncthreads();
    if (tid == 0) {
        float S = 0.f, SS = 0.f;
        #pragma unroll
        for (int i = 0; i < 8; i++) { S += shs[i]; SS += shss[i]; }
        float m = S / Dz;
        float var = SS / Dz - m * m;
        s_mean = m;
        s_rstd = 1.0f / sqrtf(var + 1e-5f);
    }
    __syncthreads();
    float m = s_mean, rs = s_rstd;
    float y0 = (v0 - m) * rs * gF[tid] + bF[tid];
    float y1 = (v1 - m) * rs * gF[tid + 256] + bF[tid + 256];
    float p = y0 * Wp[tid] + y1 * Wp[tid + 256];
    #pragma unroll
    for (int o = 16; o; o >>= 1) p += __shfl_xor_sync(0xffffffffu, p, o);
    if (lane == 0) shp[w] = p;
    __syncthreads();
    if (tid == 0) {
        float P = 0.f;
        #pragma unroll
        for (int i = 0; i < 8; i++) P += shp[i];
        g_dec[b] = P + bp[0];
    }
}

// ---------------- broadcast output: out[i][j][e] = dec[j]*std[i,e] + mean[i,e] ----------------
__global__ void out_kernel(float* __restrict__ out) {
    int idx = blockIdx.x * blockDim.x + threadIdx.x;
    if (idx >= Bz * Bz * Ez) return;
    int e = idx % Ez;
    int j = (idx / Ez) % Bz;
    int i = idx / (Ez * Bz);
    out[idx] = g_dec[j] * g_std[i * Ez + e] + g_mean[i * Ez + e];
}

// ================================================================================
extern "C" void kernel_launch(void* const* d_in, const int* in_sizes, int n_in,
                              void* d_out, int out_size) {
    const float* x_enc  = (const float*)d_in[0];
    const float* x_mark = (const float*)d_in[1];
    const float* W_emb  = (const float*)d_in[2];
    const float* b_emb  = (const float*)d_in[3];
    const float* Wqk    = (const float*)d_in[4];
    const float* Wv     = (const float*)d_in[5];
    const float* Wo     = (const float*)d_in[6];
    const float* bo     = (const float*)d_in[7];
    const float* Wc1    = (const float*)d_in[8];
    const float* bc1    = (const float*)d_in[9];
    const float* Wc2    = (const float*)d_in[10];
    const float* bc2    = (const float*)d_in[11];
    const float* g1     = (const float*)d_in[12];
    const float* b1     = (const float*)d_in[13];
    const float* g2     = (const float*)d_in[14];
    const float* b2     = (const float*)d_in[15];
    const float* gF     = (const float*)d_in[16];
    const float* bF     = (const float*)d_in[17];
    const float* Wp     = (const float*)d_in[18];
    const float* bp     = (const float*)d_in[19];
    const float* rot    = (const float*)d_in[20];
    float* out = (float*)d_out;

    float *p_tok, *p_X, *p_QK, *p_V, *p_rotT, *p_ROT, *p_AO, *p_Y, *p_H1;
    cudaGetSymbolAddress((void**)&p_tok,  g_tok);
    cudaGetSymbolAddress((void**)&p_X,    g_X);
    cudaGetSymbolAddress((void**)&p_QK,   g_QK);
    cudaGetSymbolAddress((void**)&p_V,    g_V);
    cudaGetSymbolAddress((void**)&p_rotT, g_rotT);
    cudaGetSymbolAddress((void**)&p_ROT,  g_ROT);
    cudaGetSymbolAddress((void**)&p_AO,   g_AO);
    cudaGetSymbolAddress((void**)&p_Y,    g_Y);
    cudaGetSymbolAddress((void**)&p_H1,   g_H1);

    // ---- RevIN + tokenization + embedding ----
    stats_kernel<<<2048, 256>>>(x_enc);
    tok_kernel<<<(Bz * NTOK * Lz + 255) / 256, 256>>>(x_enc, x_mark);
    zero_pad_kernel<<<(Bz * 4 * Dz + 255) / 256, 256>>>();
    // X[:, :516, :] = TOK @ W_emb^T + b_emb
    gemm128<<<dim3(Dz / 128, (Bz * NTOK + 127) / 128), 256>>>(
        p_tok, W_emb, b_emb, p_X, Bz * NTOK, Dz, Lz,
        0, 0, -1, 1, NTOK, TPAD, 0);

    for (int l = 0; l < 2; l++) {
        const float* Wqk_l = Wqk + (size_t)l * Dz * Dz;
        const float* Wv_l  = Wv  + (size_t)l * Dz * Dz;
        const float* Wo_l  = Wo  + (size_t)l * Dz * Dz;
        const float* bo_l  = bo  + (size_t)l * Dz;
        const float* Wc1_l = Wc1 + (size_t)l * DFFz * Dz;
        const float* bc1_l = bc1 + (size_t)l * DFFz;
        const float* Wc2_l = Wc2 + (size_t)l * Dz * DFFz;
        const float* bc2_l = bc2 + (size_t)l * Dz;
        const float* g1_l = g1 + (size_t)l * Dz;
        const float* b1_l = b1 + (size_t)l * Dz;
        const float* g2_l = g2 + (size_t)l * Dz;
        const float* b2_l = b2 + (size_t)l * Dz;
        const float* rot_l = rot + (size_t)l * DHz * NHASHz * (NBz / 2);

        // QK projection (head-split output [bh, t, dh])
        gemm128<<<dim3(Dz / 128, (Bz * TPAD) / 128), 256>>>(
            p_X, Wqk_l, nullptr, p_QK, Bz * TPAD, Dz, Dz,
            0, 0, -1, 2, 0, TPAD, 0);
        if (l == 0) {
            gemm128<<<dim3(Dz / 128, (Bz * TPAD) / 128), 256>>>(
                p_X, Wv_l, nullptr, p_V, Bz * TPAD, Dz, Dz,
                0, 0, -1, 2, 0, TPAD, 0);
        }

        // LSH bucketing: rotated = QK @ rotT^T, then argmax -> sort keys
        rotT_kernel<<<(ROTCP * DHz + 255) / 256, 256>>>(rot_l);
        gemm128<<<dim3(ROTCP / 128, (BHz * TPAD) / 128), 256>>>(
            p_QK, p_rotT, nullptr, p_ROT, BHz * TPAD, ROTCP, DHz,
            0, 0, -1, 0, 0, 0, 0);
        argmax_kernel<<<(BHz * TPAD * NHASHz * 32 + 255) / 256, 256>>>();
        sort_kernel<<<BHz, 1024>>>();

        if (l == 0) {
            chunk_attn_kernel<<<(BHz * NCH) / 4, 128>>>();
            combine_kernel<<<(BHz * TPAD * 64) / 256, 256>>>(-1);

            gemm128<<<dim3(Dz / 128, (Bz * NTOK + 127) / 128), 256>>>(
                p_AO, Wo_l, bo_l, p_Y, Bz * NTOK, Dz, Dz,
                NTOK, TPAD, -1, 0, 0, 0, 0);
            ln_res_kernel<<<Bz * NTOK, 256>>>(g1_l, b1_l, -1);
            gemm128<<<dim3(DFFz / 128, (Bz * NTOK + 127) / 128), 256>>>(
                p_X, Wc1_l, bc1_l, p_H1, Bz * NTOK, DFFz, Dz,
                NTOK, TPAD, -1, 0, 0, 0, 1);
            gemm128<<<dim3(Dz / 128, (Bz * NTOK + 127) / 128), 256>>>(
                p_H1, Wc2_l, bc2_l, p_Y, Bz * NTOK, Dz, DFFz,
                0, 0, -1, 0, 0, 0, 0);
            ln_res_kernel<<<Bz * NTOK, 256>>>(g2_l, b2_l, -1);
        } else {
            // last layer: only token 515 feeds the output head.
            // sparse attention: only the 4 chunks (per bh) containing token 515,
            // V rows computed on the fly (V GEMM skipped entirely).
            find_sel_kernel<<<BHz, 256>>>();
            chunk_attn_sel_kernel<<<(BHz * NHASHz * 32 + 127) / 128, 128>>>(Wv_l);
            combine_kernel<<<(BHz * 64) / 256, 256>>>(NTOK - 1);

            gemm128<<<dim3(Dz / 128, 1), 256>>>(
                p_AO, Wo_l, bo_l, p_Y, Bz, Dz, Dz,
                0, TPAD, NTOK - 1, 0, 0, 0, 0);
            ln_res_kernel<<<Bz, 256>>>(g1_l, b1_l, NTOK - 1);
            gemm128<<<dim3(DFFz / 128, 1), 256>>>(
                p_X, Wc1_l, bc1_l, p_H1, Bz, DFFz, Dz,
                0, TPAD, NTOK - 1, 0, 0, 0, 1);
            gemm128<<<dim3(Dz / 128, 1), 256>>>(
                p_H1, Wc2_l, bc2_l, p_Y, Bz, Dz, DFFz,
                0, 0, -1, 0, 0, 0, 0);
            ln_res_kernel<<<Bz, 256>>>(g2_l, b2_l, NTOK - 1);
        }
    }

    final_kernel<<<Bz, 256>>>(gF, bF, Wp, bp);
    out_kernel<<<(Bz * Bz * Ez + 255) / 256, 256>>>(out);
}